// round 2
// baseline (speedup 1.0000x reference)
#include <cuda_runtime.h>
#include <math.h>
#include <stdint.h>

// Problem constants
#define B   8
#define NQ  300
#define NK  4096
#define E   256
#define H   8
#define D   32
#define FF  2048
#define LAYERS 6
#define ATTN_SCALE 0.17677669529663687f   // 1/sqrt(32)

// ---------------- scratch (static device globals; no allocation) ----------------
__device__ float g_t[B * NQ * E];          // running tgt
__device__ float g_qkv[B * NQ * 3 * E];    // SA qkv
__device__ float g_attn[B * NQ * E];       // attention context (merged heads)
__device__ float g_proj[B * NQ * E];       // projection output / residual branch
__device__ float g_q[B * NQ * E];          // CA q
__device__ float g_k[B * NK * E];          // CA k
__device__ float g_v[B * NK * E];          // CA v
__device__ float g_ffn[B * NQ * FF];       // FFN hidden

// ---------------- copy kernel ----------------
__global__ void copy_kernel(const float* __restrict__ src, float* __restrict__ dst, int n) {
    int i = blockIdx.x * blockDim.x + threadIdx.x;
    if (i < n) dst[i] = src[i];
}

// ---------------- GEMM: C[M,N] = A[M,K] @ W[N,K]^T + bias, optional ReLU ----------------
// BM=BN=64, BK=16, 256 threads, 4x4 micro-tile per thread.
template <int RELU>
__global__ void gemm_bias_kernel(const float* __restrict__ A,
                                 const float* __restrict__ W,
                                 const float* __restrict__ bias,
                                 float* __restrict__ C,
                                 int M, int N, int K) {
    __shared__ float As[16][64];
    __shared__ float Ws[16][64];
    const int tid = threadIdx.x;
    const int m0 = blockIdx.y * 64;
    const int n0 = blockIdx.x * 64;
    const int tm = (tid >> 4) << 2;
    const int tn = (tid & 15) << 2;

    float acc[4][4] = {};

    for (int k0 = 0; k0 < K; k0 += 16) {
#pragma unroll
        for (int i = 0; i < 4; i++) {
            int idx = tid + i * 256;
            int r = idx >> 4;
            int c = idx & 15;
            int m = m0 + r;
            As[c][r] = (m < M) ? A[(size_t)m * K + k0 + c] : 0.f;
            Ws[c][r] = W[(size_t)(n0 + r) * K + k0 + c];
        }
        __syncthreads();
#pragma unroll
        for (int kk = 0; kk < 16; kk++) {
            float a[4], b[4];
#pragma unroll
            for (int i = 0; i < 4; i++) a[i] = As[kk][tm + i];
#pragma unroll
            for (int j = 0; j < 4; j++) b[j] = Ws[kk][tn + j];
#pragma unroll
            for (int i = 0; i < 4; i++)
#pragma unroll
                for (int j = 0; j < 4; j++)
                    acc[i][j] += a[i] * b[j];
        }
        __syncthreads();
    }

#pragma unroll
    for (int i = 0; i < 4; i++) {
        int m = m0 + tm + i;
        if (m >= M) continue;
#pragma unroll
        for (int j = 0; j < 4; j++) {
            int n = n0 + tn + j;
            float v = acc[i][j] + bias[n];
            if (RELU) v = fmaxf(v, 0.f);
            C[(size_t)m * N + n] = v;
        }
    }
}

// ---------------- Self-attention: one block per (b, h, q), 128 threads ----------------
__global__ void sa_attn_kernel(const float* __restrict__ qkv, float* __restrict__ out) {
    const int q = blockIdx.x, h = blockIdx.y, b = blockIdx.z;
    const int tid = threadIdx.x;
    __shared__ float qs[D];
    __shared__ float sc[NQ];
    __shared__ float red[128];
    __shared__ float part[4][D];

    const float* qrow = qkv + (size_t)(b * NQ + q) * (3 * E) + h * D;
    if (tid < D) qs[tid] = qrow[tid];
    __syncthreads();

    for (int j = tid; j < NQ; j += 128) {
        const float* krow = qkv + (size_t)(b * NQ + j) * (3 * E) + E + h * D;
        float s = 0.f;
#pragma unroll
        for (int d = 0; d < D; d++) s += qs[d] * krow[d];
        sc[j] = s * ATTN_SCALE;
    }
    __syncthreads();

    float m = -INFINITY;
    for (int j = tid; j < NQ; j += 128) m = fmaxf(m, sc[j]);
    red[tid] = m;
    __syncthreads();
    for (int s = 64; s > 0; s >>= 1) {
        if (tid < s) red[tid] = fmaxf(red[tid], red[tid + s]);
        __syncthreads();
    }
    m = red[0];
    __syncthreads();

    float sum = 0.f;
    for (int j = tid; j < NQ; j += 128) {
        float e = expf(sc[j] - m);
        sc[j] = e;
        sum += e;
    }
    red[tid] = sum;
    __syncthreads();
    for (int s = 64; s > 0; s >>= 1) {
        if (tid < s) red[tid] += red[tid + s];
        __syncthreads();
    }
    float inv = 1.f / red[0];
    __syncthreads();

    const int lane = tid & 31, grp = tid >> 5;
    float acc = 0.f;
    for (int j = grp; j < NQ; j += 4) {
        const float* vrow = qkv + (size_t)(b * NQ + j) * (3 * E) + 2 * E + h * D;
        acc += sc[j] * vrow[lane];
    }
    part[grp][lane] = acc;
    __syncthreads();
    if (tid < D) {
        float o = (part[0][tid] + part[1][tid] + part[2][tid] + part[3][tid]) * inv;
        out[(size_t)(b * NQ + q) * E + h * D + tid] = o;
    }
}

// ---------------- Cross-attention with mask (int32): one block per (b, h, q), 256 threads ---
__global__ void ca_attn_kernel(const float* __restrict__ Q,
                               const float* __restrict__ Kb,
                               const float* __restrict__ Vb,
                               const int* __restrict__ mask,
                               float* __restrict__ out) {
    const int q = blockIdx.x, h = blockIdx.y, b = blockIdx.z;
    const int tid = threadIdx.x;
    __shared__ float qs[D];
    __shared__ float sc[NK];
    __shared__ float red[256];
    __shared__ float part[8][D];

    if (tid < D) qs[tid] = Q[(size_t)(b * NQ + q) * E + h * D + tid];
    __syncthreads();

    const int* mrow = mask + (size_t)(b * NQ + q) * NK;
    for (int j = tid; j < NK; j += 256) {
        float s;
        if (mrow[j]) {
            const float* krow = Kb + (size_t)(b * NK + j) * E + h * D;
            s = 0.f;
#pragma unroll
            for (int d = 0; d < D; d++) s += qs[d] * krow[d];
            s *= ATTN_SCALE;
        } else {
            s = -INFINITY;
        }
        sc[j] = s;
    }
    __syncthreads();

    float m = -INFINITY;
    for (int j = tid; j < NK; j += 256) m = fmaxf(m, sc[j]);
    red[tid] = m;
    __syncthreads();
    for (int s = 128; s > 0; s >>= 1) {
        if (tid < s) red[tid] = fmaxf(red[tid], red[tid + s]);
        __syncthreads();
    }
    m = red[0];
    __syncthreads();

    float sum = 0.f;
    for (int j = tid; j < NK; j += 256) {
        float sj = sc[j];
        float e = (sj == -INFINITY) ? 0.f : expf(sj - m);
        sc[j] = e;
        sum += e;
    }
    red[tid] = sum;
    __syncthreads();
    for (int s = 128; s > 0; s >>= 1) {
        if (tid < s) red[tid] += red[tid + s];
        __syncthreads();
    }
    float denom = red[0];
    float inv = (denom > 0.f) ? 1.f / denom : 0.f;
    __syncthreads();

    const int lane = tid & 31, grp = tid >> 5;  // 8 groups x 32 lanes
    float acc = 0.f;
    for (int j = grp; j < NK; j += 8) {
        acc += sc[j] * Vb[(size_t)(b * NK + j) * E + h * D + lane];
    }
    part[grp][lane] = acc;
    __syncthreads();
    if (tid < D) {
        float o = 0.f;
#pragma unroll
        for (int g = 0; g < 8; g++) o += part[g][tid];
        out[(size_t)(b * NQ + q) * E + h * D + tid] = o * inv;
    }
}

// ---------------- LayerNorm (+ optional residual): one block (256 thr) per row ----------------
__global__ void ln_kernel(const float* __restrict__ x,
                          const float* __restrict__ res,   // may be null
                          const float* __restrict__ gamma,
                          const float* __restrict__ beta,
                          float* __restrict__ out) {
    const int row = blockIdx.x;
    const int tid = threadIdx.x;   // 0..255 == E
    __shared__ float red[E];

    float v = x[(size_t)row * E + tid];
    if (res) v += res[(size_t)row * E + tid];

    red[tid] = v;
    __syncthreads();
    for (int s = 128; s > 0; s >>= 1) {
        if (tid < s) red[tid] += red[tid + s];
        __syncthreads();
    }
    float mean = red[0] * (1.f / E);
    __syncthreads();

    float d = v - mean;
    red[tid] = d * d;
    __syncthreads();
    for (int s = 128; s > 0; s >>= 1) {
        if (tid < s) red[tid] += red[tid + s];
        __syncthreads();
    }
    float var = red[0] * (1.f / E);
    float o = d * rsqrtf(var + 1e-5f) * gamma[tid] + beta[tid];
    out[(size_t)row * E + tid] = o;
}

// ---------------- host-side launch helpers ----------------
static inline void launch_gemm(const float* A, const float* W, const float* bias,
                               float* C, int M, int N, int K, bool relu) {
    dim3 grid(N / 64, (M + 63) / 64);
    if (relu)
        gemm_bias_kernel<1><<<grid, 256>>>(A, W, bias, C, M, N, K);
    else
        gemm_bias_kernel<0><<<grid, 256>>>(A, W, bias, C, M, N, K);
}

extern "C" void kernel_launch(void* const* d_in, const int* in_sizes, int n_in,
                              void* d_out, int out_size) {
    const float* tgt      = (const float*)d_in[0];
    const float* memory   = (const float*)d_in[1];
    const int*   gmask    = (const int*)d_in[2];     // bool stored as int32
    const float* sa_wqkv  = (const float*)d_in[3];
    const float* sa_bqkv  = (const float*)d_in[4];
    const float* sa_wo    = (const float*)d_in[5];
    const float* sa_bo    = (const float*)d_in[6];
    const float* ca_wq    = (const float*)d_in[7];
    const float* ca_bq    = (const float*)d_in[8];
    const float* ca_wk    = (const float*)d_in[9];
    const float* ca_bk    = (const float*)d_in[10];
    const float* ca_wv    = (const float*)d_in[11];
    const float* ca_bv    = (const float*)d_in[12];
    const float* ca_wo    = (const float*)d_in[13];
    const float* ca_bo    = (const float*)d_in[14];
    const float* f_w1     = (const float*)d_in[15];
    const float* f_b1     = (const float*)d_in[16];
    const float* f_w2     = (const float*)d_in[17];
    const float* f_b2     = (const float*)d_in[18];
    const float* ln1g     = (const float*)d_in[19];
    const float* ln1b     = (const float*)d_in[20];
    const float* ln2g     = (const float*)d_in[21];
    const float* ln2b     = (const float*)d_in[22];
    const float* ln3g     = (const float*)d_in[23];
    const float* ln3b     = (const float*)d_in[24];
    const float* lnfg     = (const float*)d_in[25];
    const float* lnfb     = (const float*)d_in[26];

    float* t    = nullptr;  cudaGetSymbolAddress((void**)&t,    g_t);
    float* qkv  = nullptr;  cudaGetSymbolAddress((void**)&qkv,  g_qkv);
    float* attn = nullptr;  cudaGetSymbolAddress((void**)&attn, g_attn);
    float* proj = nullptr;  cudaGetSymbolAddress((void**)&proj, g_proj);
    float* qb   = nullptr;  cudaGetSymbolAddress((void**)&qb,   g_q);
    float* kb   = nullptr;  cudaGetSymbolAddress((void**)&kb,   g_k);
    float* vb   = nullptr;  cudaGetSymbolAddress((void**)&vb,   g_v);
    float* ffn  = nullptr;  cudaGetSymbolAddress((void**)&ffn,  g_ffn);

    const int MQ = B * NQ;   // 2400
    const int MK = B * NK;   // 32768

    copy_kernel<<<(MQ * E + 255) / 256, 256>>>(tgt, t, MQ * E);

    dim3 sa_grid(NQ, H, B);
    dim3 ca_grid(NQ, H, B);

    for (int l = 0; l < LAYERS; l++) {
        const float* wqkv = sa_wqkv + (size_t)l * 3 * E * E;
        const float* bqkv = sa_bqkv + (size_t)l * 3 * E;
        const float* wo   = sa_wo   + (size_t)l * E * E;
        const float* bo   = sa_bo   + (size_t)l * E;
        const float* wq   = ca_wq   + (size_t)l * E * E;
        const float* bq   = ca_bq   + (size_t)l * E;
        const float* wk   = ca_wk   + (size_t)l * E * E;
        const float* bk   = ca_bk   + (size_t)l * E;
        const float* wv   = ca_wv   + (size_t)l * E * E;
        const float* bv   = ca_bv   + (size_t)l * E;
        const float* wco  = ca_wo   + (size_t)l * E * E;
        const float* bco  = ca_bo   + (size_t)l * E;
        const float* w1   = f_w1    + (size_t)l * FF * E;
        const float* b1   = f_b1    + (size_t)l * FF;
        const float* w2   = f_w2    + (size_t)l * E * FF;
        const float* b2   = f_b2    + (size_t)l * E;
        const float* g1   = ln1g + (size_t)l * E;
        const float* be1  = ln1b + (size_t)l * E;
        const float* g2   = ln2g + (size_t)l * E;
        const float* be2  = ln2b + (size_t)l * E;
        const float* g3   = ln3g + (size_t)l * E;
        const float* be3  = ln3b + (size_t)l * E;

        // --- self-attention ---
        launch_gemm(t, wqkv, bqkv, qkv, MQ, 3 * E, E, false);
        sa_attn_kernel<<<sa_grid, 128>>>(qkv, attn);
        launch_gemm(attn, wo, bo, proj, MQ, E, E, false);
        ln_kernel<<<MQ, E>>>(t, proj, g1, be1, t);

        // --- cross-attention ---
        launch_gemm(t, wq, bq, qb, MQ, E, E, false);
        launch_gemm(memory, wk, bk, kb, MK, E, E, false);
        launch_gemm(memory, wv, bv, vb, MK, E, E, false);
        ca_attn_kernel<<<ca_grid, 256>>>(qb, kb, vb, gmask, attn);
        launch_gemm(attn, wco, bco, proj, MQ, E, E, false);
        ln_kernel<<<MQ, E>>>(t, proj, g2, be2, t);

        // --- FFN ---
        launch_gemm(t, w1, b1, ffn, MQ, FF, E, true);
        launch_gemm(ffn, w2, b2, proj, MQ, E, FF, false);
        ln_kernel<<<MQ, E>>>(t, proj, g3, be3, t);
    }

    ln_kernel<<<MQ, E>>>(t, nullptr, lnfg, lnfb, (float*)d_out);
}

// round 3
// speedup vs baseline: 2.8396x; 2.8396x over previous
#include <cuda_runtime.h>
#include <math.h>
#include <stdint.h>

// Problem constants
#define B   8
#define NQ  300
#define NK  4096
#define E   256
#define H   8
#define D   32
#define FF  2048
#define LAYERS 6
#define ATTN_SCALE 0.17677669529663687f   // 1/sqrt(32)

#define TQ 16      // CA query tile
#define CK 128     // CA key chunk

// ---------------- scratch (static device globals; no allocation) ----------------
__device__ float g_t[B * NQ * E];
__device__ float g_qkv[B * NQ * 3 * E];
__device__ float g_attn[B * NQ * E];
__device__ float g_proj[B * NQ * E];
__device__ float g_q[B * NQ * E];
__device__ float g_k[B * NK * E];
__device__ float g_v[B * NK * E];
__device__ float g_ffn[B * NQ * FF];

// ---------------- copy kernel ----------------
__global__ void copy_kernel(const float* __restrict__ src, float* __restrict__ dst, int n) {
    int i = blockIdx.x * blockDim.x + threadIdx.x;
    if (i < n) dst[i] = src[i];
}

// ---------------- GEMM 64x64x16 (for small shapes) ----------------
template <int RELU>
__global__ void gemm_bias_kernel(const float* __restrict__ A,
                                 const float* __restrict__ W,
                                 const float* __restrict__ bias,
                                 float* __restrict__ C,
                                 int M, int N, int K) {
    __shared__ float As[16][64];
    __shared__ float Ws[16][64];
    const int tid = threadIdx.x;
    const int m0 = blockIdx.y * 64;
    const int n0 = blockIdx.x * 64;
    const int tm = (tid >> 4) << 2;
    const int tn = (tid & 15) << 2;

    float acc[4][4] = {};

    for (int k0 = 0; k0 < K; k0 += 16) {
#pragma unroll
        for (int i = 0; i < 4; i++) {
            int idx = tid + i * 256;
            int r = idx >> 4;
            int c = idx & 15;
            int m = m0 + r;
            As[c][r] = (m < M) ? A[(size_t)m * K + k0 + c] : 0.f;
            Ws[c][r] = W[(size_t)(n0 + r) * K + k0 + c];
        }
        __syncthreads();
#pragma unroll
        for (int kk = 0; kk < 16; kk++) {
            float a[4], b[4];
#pragma unroll
            for (int i = 0; i < 4; i++) a[i] = As[kk][tm + i];
#pragma unroll
            for (int j = 0; j < 4; j++) b[j] = Ws[kk][tn + j];
#pragma unroll
            for (int i = 0; i < 4; i++)
#pragma unroll
                for (int j = 0; j < 4; j++)
                    acc[i][j] += a[i] * b[j];
        }
        __syncthreads();
    }

#pragma unroll
    for (int i = 0; i < 4; i++) {
        int m = m0 + tm + i;
        if (m >= M) continue;
#pragma unroll
        for (int j = 0; j < 4; j++) {
            int n = n0 + tn + j;
            float v = acc[i][j] + bias[n];
            if (RELU) v = fmaxf(v, 0.f);
            C[(size_t)m * N + n] = v;
        }
    }
}

// ---------------- GEMM 128x128x16, double-buffered, float4 ----------------
// Requires N % 128 == 0, K % 16 == 0. M guarded.
template <int RELU>
__global__ void __launch_bounds__(256, 2)
gemm128_kernel(const float* __restrict__ A,
               const float* __restrict__ W,
               const float* __restrict__ bias,
               float* __restrict__ C,
               int M, int N, int K) {
    __shared__ __align__(16) float As[2][16 * 132];
    __shared__ __align__(16) float Ws[2][16 * 132];
    const int tid = threadIdx.x;
    const int m0 = blockIdx.y * 128;
    const int n0 = blockIdx.x * 128;
    const int tm = (tid >> 4) << 3;
    const int tn = (tid & 15) << 3;

    float acc[8][8] = {};
    float4 pa[2], pw[2];

    // prologue: load tile 0
#pragma unroll
    for (int i = 0; i < 2; i++) {
        int fidx = i * 256 + tid;
        int r = fidx >> 2, c = fidx & 3;
        int m = m0 + r;
        pa[i] = (m < M) ? *(const float4*)&A[(size_t)m * K + c * 4]
                        : make_float4(0.f, 0.f, 0.f, 0.f);
        pw[i] = *(const float4*)&W[(size_t)(n0 + r) * K + c * 4];
    }
#pragma unroll
    for (int i = 0; i < 2; i++) {
        int fidx = i * 256 + tid;
        int r = fidx >> 2, c = fidx & 3;
        As[0][(c * 4 + 0) * 132 + r] = pa[i].x;
        As[0][(c * 4 + 1) * 132 + r] = pa[i].y;
        As[0][(c * 4 + 2) * 132 + r] = pa[i].z;
        As[0][(c * 4 + 3) * 132 + r] = pa[i].w;
        Ws[0][(c * 4 + 0) * 132 + r] = pw[i].x;
        Ws[0][(c * 4 + 1) * 132 + r] = pw[i].y;
        Ws[0][(c * 4 + 2) * 132 + r] = pw[i].z;
        Ws[0][(c * 4 + 3) * 132 + r] = pw[i].w;
    }
    __syncthreads();

    const int nt = K / 16;
    for (int t = 0; t < nt; t++) {
        const int cur = t & 1;
        if (t + 1 < nt) {
            int k0 = (t + 1) * 16;
#pragma unroll
            for (int i = 0; i < 2; i++) {
                int fidx = i * 256 + tid;
                int r = fidx >> 2, c = fidx & 3;
                int m = m0 + r;
                pa[i] = (m < M) ? *(const float4*)&A[(size_t)m * K + k0 + c * 4]
                                : make_float4(0.f, 0.f, 0.f, 0.f);
                pw[i] = *(const float4*)&W[(size_t)(n0 + r) * K + k0 + c * 4];
            }
        }
#pragma unroll
        for (int kk = 0; kk < 16; kk++) {
            float4 a0 = *(const float4*)&As[cur][kk * 132 + tm];
            float4 a1 = *(const float4*)&As[cur][kk * 132 + tm + 4];
            float4 b0 = *(const float4*)&Ws[cur][kk * 132 + tn];
            float4 b1 = *(const float4*)&Ws[cur][kk * 132 + tn + 4];
            float av[8] = {a0.x, a0.y, a0.z, a0.w, a1.x, a1.y, a1.z, a1.w};
            float bv[8] = {b0.x, b0.y, b0.z, b0.w, b1.x, b1.y, b1.z, b1.w};
#pragma unroll
            for (int i = 0; i < 8; i++)
#pragma unroll
                for (int j = 0; j < 8; j++)
                    acc[i][j] += av[i] * bv[j];
        }
        if (t + 1 < nt) {
            __syncthreads();
            const int nxt = cur ^ 1;
#pragma unroll
            for (int i = 0; i < 2; i++) {
                int fidx = i * 256 + tid;
                int r = fidx >> 2, c = fidx & 3;
                As[nxt][(c * 4 + 0) * 132 + r] = pa[i].x;
                As[nxt][(c * 4 + 1) * 132 + r] = pa[i].y;
                As[nxt][(c * 4 + 2) * 132 + r] = pa[i].z;
                As[nxt][(c * 4 + 3) * 132 + r] = pa[i].w;
                Ws[nxt][(c * 4 + 0) * 132 + r] = pw[i].x;
                Ws[nxt][(c * 4 + 1) * 132 + r] = pw[i].y;
                Ws[nxt][(c * 4 + 2) * 132 + r] = pw[i].z;
                Ws[nxt][(c * 4 + 3) * 132 + r] = pw[i].w;
            }
            __syncthreads();
        }
    }

    // epilogue
    float4 bs0 = *(const float4*)&bias[n0 + tn];
    float4 bs1 = *(const float4*)&bias[n0 + tn + 4];
    float bb[8] = {bs0.x, bs0.y, bs0.z, bs0.w, bs1.x, bs1.y, bs1.z, bs1.w};
#pragma unroll
    for (int i = 0; i < 8; i++) {
        int m = m0 + tm + i;
        if (m >= M) continue;
        float o[8];
#pragma unroll
        for (int j = 0; j < 8; j++) {
            float v = acc[i][j] + bb[j];
            if (RELU) v = fmaxf(v, 0.f);
            o[j] = v;
        }
        *(float4*)&C[(size_t)m * N + n0 + tn]     = make_float4(o[0], o[1], o[2], o[3]);
        *(float4*)&C[(size_t)m * N + n0 + tn + 4] = make_float4(o[4], o[5], o[6], o[7]);
    }
}

// ---------------- Self-attention: one block per (b, h, q), 128 threads ----------------
__global__ void sa_attn_kernel(const float* __restrict__ qkv, float* __restrict__ out) {
    const int q = blockIdx.x, h = blockIdx.y, b = blockIdx.z;
    const int tid = threadIdx.x;
    __shared__ float qs[D];
    __shared__ float sc[NQ];
    __shared__ float red[128];
    __shared__ float part[4][D];

    const float* qrow = qkv + (size_t)(b * NQ + q) * (3 * E) + h * D;
    if (tid < D) qs[tid] = qrow[tid];
    __syncthreads();

    for (int j = tid; j < NQ; j += 128) {
        const float* krow = qkv + (size_t)(b * NQ + j) * (3 * E) + E + h * D;
        float s = 0.f;
#pragma unroll
        for (int d = 0; d < D; d++) s += qs[d] * krow[d];
        sc[j] = s * ATTN_SCALE;
    }
    __syncthreads();

    float m = -INFINITY;
    for (int j = tid; j < NQ; j += 128) m = fmaxf(m, sc[j]);
    red[tid] = m;
    __syncthreads();
    for (int s = 64; s > 0; s >>= 1) {
        if (tid < s) red[tid] = fmaxf(red[tid], red[tid + s]);
        __syncthreads();
    }
    m = red[0];
    __syncthreads();

    float sum = 0.f;
    for (int j = tid; j < NQ; j += 128) {
        float e = __expf(sc[j] - m);
        sc[j] = e;
        sum += e;
    }
    red[tid] = sum;
    __syncthreads();
    for (int s = 64; s > 0; s >>= 1) {
        if (tid < s) red[tid] += red[tid + s];
        __syncthreads();
    }
    float inv = 1.f / red[0];
    __syncthreads();

    const int lane = tid & 31, grp = tid >> 5;
    float acc = 0.f;
    for (int j = grp; j < NQ; j += 4) {
        const float* vrow = qkv + (size_t)(b * NQ + j) * (3 * E) + 2 * E + h * D;
        acc += sc[j] * vrow[lane];
    }
    part[grp][lane] = acc;
    __syncthreads();
    if (tid < D) {
        float o = (part[0][tid] + part[1][tid] + part[2][tid] + part[3][tid]) * inv;
        out[(size_t)(b * NQ + q) * E + h * D + tid] = o;
    }
}

// ---------------- Cross-attention, flash-style: one block per (b, h, qtile) ----------------
// 256 threads = 8 warps; each warp owns 2 queries; K/V chunk of 128 staged in smem.
__global__ void __launch_bounds__(256)
ca_flash_kernel(const float* __restrict__ Q,
                const float* __restrict__ Kb,
                const float* __restrict__ Vb,
                const int* __restrict__ mask,
                float* __restrict__ out) {
    const int qt = blockIdx.x, h = blockIdx.y, b = blockIdx.z;
    const int tid = threadIdx.x;
    const int w = tid >> 5, lane = tid & 31;

    __shared__ __align__(16) float Ks[CK * 36];
    __shared__ __align__(16) float Vs[CK * 36];
    __shared__ __align__(16) float Qs[TQ * 36];
    __shared__ float Ps[8][CK];

    // load Q tile (clamped)
    for (int i = tid; i < TQ * D; i += 256) {
        int ql = i >> 5, d = i & 31;
        int qg = qt * TQ + ql;
        if (qg >= NQ) qg = NQ - 1;
        Qs[ql * 36 + d] = Q[(size_t)(b * NQ + qg) * E + h * D + d];
    }
    __syncthreads();

    const int q0g = qt * TQ + w * 2;
    const int q1g = q0g + 1;
    const int q0c = (q0g < NQ) ? q0g : NQ - 1;
    const int q1c = (q1g < NQ) ? q1g : NQ - 1;
    const int* mrow[2] = { mask + (size_t)(b * NQ + q0c) * NK,
                           mask + (size_t)(b * NQ + q1c) * NK };

    float mv[2] = {-INFINITY, -INFINITY};
    float sv[2] = {0.f, 0.f};
    float av[2] = {0.f, 0.f};

    for (int k0 = 0; k0 < NK; k0 += CK) {
        // stage K,V chunk
        for (int i = tid; i < CK * 8; i += 256) {
            int j = i >> 3, d4 = i & 7;
            size_t base = (size_t)(b * NK + k0 + j) * E + h * D + d4 * 4;
            *(float4*)&Ks[j * 36 + d4 * 4] = *(const float4*)&Kb[base];
            *(float4*)&Vs[j * 36 + d4 * 4] = *(const float4*)&Vb[base];
        }
        __syncthreads();

#pragma unroll
        for (int sub = 0; sub < 2; sub++) {
            const int ql = w * 2 + sub;
            float sc[4];
#pragma unroll
            for (int c = 0; c < 4; c++) {
                int key = c * 32 + lane;
                int mk = mrow[sub][k0 + key];
                float s;
                if (mk) {
                    s = 0.f;
#pragma unroll
                    for (int d4 = 0; d4 < 8; d4++) {
                        float4 kk = *(const float4*)&Ks[key * 36 + d4 * 4];
                        float4 qq = *(const float4*)&Qs[ql * 36 + d4 * 4];
                        s += kk.x * qq.x + kk.y * qq.y + kk.z * qq.z + kk.w * qq.w;
                    }
                    s *= ATTN_SCALE;
                } else {
                    s = -INFINITY;
                }
                sc[c] = s;
            }
            float cmax = fmaxf(fmaxf(sc[0], sc[1]), fmaxf(sc[2], sc[3]));
#pragma unroll
            for (int o = 16; o > 0; o >>= 1)
                cmax = fmaxf(cmax, __shfl_xor_sync(0xffffffff, cmax, o));

            float mOld = mv[sub];
            float mNew = fmaxf(mOld, cmax);
            float factor, psum = 0.f;
            if (mNew == -INFINITY) {
                factor = 1.f;
#pragma unroll
                for (int c = 0; c < 4; c++) Ps[w][c * 32 + lane] = 0.f;
            } else {
                factor = __expf(mOld - mNew);   // exp(-inf)=0 when mOld=-inf
#pragma unroll
                for (int c = 0; c < 4; c++) {
                    float p = (sc[c] == -INFINITY) ? 0.f : __expf(sc[c] - mNew);
                    psum += p;
                    Ps[w][c * 32 + lane] = p;
                }
            }
#pragma unroll
            for (int o = 16; o > 0; o >>= 1)
                psum += __shfl_xor_sync(0xffffffff, psum, o);
            __syncwarp();

            // V accumulation: lane = d
            float a = av[sub] * factor;
#pragma unroll 4
            for (int j = 0; j < CK; j++)
                a += Ps[w][j] * Vs[j * 36 + lane];

            av[sub] = a;
            mv[sub] = mNew;
            sv[sub] = sv[sub] * factor + psum;
            __syncwarp();
        }
        __syncthreads();
    }

    if (q0g < NQ) {
        float inv = (sv[0] > 0.f) ? 1.f / sv[0] : 0.f;
        out[(size_t)(b * NQ + q0g) * E + h * D + lane] = av[0] * inv;
    }
    if (q1g < NQ) {
        float inv = (sv[1] > 0.f) ? 1.f / sv[1] : 0.f;
        out[(size_t)(b * NQ + q1g) * E + h * D + lane] = av[1] * inv;
    }
}

// ---------------- LayerNorm (+ optional residual): one block (256 thr) per row ----------------
__global__ void ln_kernel(const float* __restrict__ x,
                          const float* __restrict__ res,
                          const float* __restrict__ gamma,
                          const float* __restrict__ beta,
                          float* __restrict__ out) {
    const int row = blockIdx.x;
    const int tid = threadIdx.x;
    __shared__ float red[E];

    float v = x[(size_t)row * E + tid];
    if (res) v += res[(size_t)row * E + tid];

    red[tid] = v;
    __syncthreads();
    for (int s = 128; s > 0; s >>= 1) {
        if (tid < s) red[tid] += red[tid + s];
        __syncthreads();
    }
    float mean = red[0] * (1.f / E);
    __syncthreads();

    float d = v - mean;
    red[tid] = d * d;
    __syncthreads();
    for (int s = 128; s > 0; s >>= 1) {
        if (tid < s) red[tid] += red[tid + s];
        __syncthreads();
    }
    float var = red[0] * (1.f / E);
    float o = d * rsqrtf(var + 1e-5f) * gamma[tid] + beta[tid];
    out[(size_t)row * E + tid] = o;
}

// ---------------- host-side launch helpers ----------------
static inline void launch_gemm(const float* A, const float* W, const float* bias,
                               float* C, int M, int N, int K, bool relu) {
    if ((N % 128) == 0 && (K % 16) == 0) {
        int blocks = (N / 128) * ((M + 127) / 128);
        if (blocks >= 76) {
            dim3 grid(N / 128, (M + 127) / 128);
            if (relu) gemm128_kernel<1><<<grid, 256>>>(A, W, bias, C, M, N, K);
            else      gemm128_kernel<0><<<grid, 256>>>(A, W, bias, C, M, N, K);
            return;
        }
    }
    dim3 grid(N / 64, (M + 63) / 64);
    if (relu) gemm_bias_kernel<1><<<grid, 256>>>(A, W, bias, C, M, N, K);
    else      gemm_bias_kernel<0><<<grid, 256>>>(A, W, bias, C, M, N, K);
}

extern "C" void kernel_launch(void* const* d_in, const int* in_sizes, int n_in,
                              void* d_out, int out_size) {
    const float* tgt      = (const float*)d_in[0];
    const float* memory   = (const float*)d_in[1];
    const int*   gmask    = (const int*)d_in[2];
    const float* sa_wqkv  = (const float*)d_in[3];
    const float* sa_bqkv  = (const float*)d_in[4];
    const float* sa_wo    = (const float*)d_in[5];
    const float* sa_bo    = (const float*)d_in[6];
    const float* ca_wq    = (const float*)d_in[7];
    const float* ca_bq    = (const float*)d_in[8];
    const float* ca_wk    = (const float*)d_in[9];
    const float* ca_bk    = (const float*)d_in[10];
    const float* ca_wv    = (const float*)d_in[11];
    const float* ca_bv    = (const float*)d_in[12];
    const float* ca_wo    = (const float*)d_in[13];
    const float* ca_bo    = (const float*)d_in[14];
    const float* f_w1     = (const float*)d_in[15];
    const float* f_b1     = (const float*)d_in[16];
    const float* f_w2     = (const float*)d_in[17];
    const float* f_b2     = (const float*)d_in[18];
    const float* ln1g     = (const float*)d_in[19];
    const float* ln1b     = (const float*)d_in[20];
    const float* ln2g     = (const float*)d_in[21];
    const float* ln2b     = (const float*)d_in[22];
    const float* ln3g     = (const float*)d_in[23];
    const float* ln3b     = (const float*)d_in[24];
    const float* lnfg     = (const float*)d_in[25];
    const float* lnfb     = (const float*)d_in[26];

    float* t    = nullptr;  cudaGetSymbolAddress((void**)&t,    g_t);
    float* qkv  = nullptr;  cudaGetSymbolAddress((void**)&qkv,  g_qkv);
    float* attn = nullptr;  cudaGetSymbolAddress((void**)&attn, g_attn);
    float* proj = nullptr;  cudaGetSymbolAddress((void**)&proj, g_proj);
    float* qb   = nullptr;  cudaGetSymbolAddress((void**)&qb,   g_q);
    float* kb   = nullptr;  cudaGetSymbolAddress((void**)&kb,   g_k);
    float* vb   = nullptr;  cudaGetSymbolAddress((void**)&vb,   g_v);
    float* ffn  = nullptr;  cudaGetSymbolAddress((void**)&ffn,  g_ffn);

    const int MQ = B * NQ;   // 2400
    const int MK = B * NK;   // 32768

    copy_kernel<<<(MQ * E + 255) / 256, 256>>>(tgt, t, MQ * E);

    dim3 sa_grid(NQ, H, B);
    dim3 ca_grid((NQ + TQ - 1) / TQ, H, B);

    for (int l = 0; l < LAYERS; l++) {
        const float* wqkv = sa_wqkv + (size_t)l * 3 * E * E;
        const float* bqkv = sa_bqkv + (size_t)l * 3 * E;
        const float* wo   = sa_wo   + (size_t)l * E * E;
        const float* bo   = sa_bo   + (size_t)l * E;
        const float* wq   = ca_wq   + (size_t)l * E * E;
        const float* bq   = ca_bq   + (size_t)l * E;
        const float* wk   = ca_wk   + (size_t)l * E * E;
        const float* bk   = ca_bk   + (size_t)l * E;
        const float* wv   = ca_wv   + (size_t)l * E * E;
        const float* bv   = ca_bv   + (size_t)l * E;
        const float* wco  = ca_wo   + (size_t)l * E * E;
        const float* bco  = ca_bo   + (size_t)l * E;
        const float* w1   = f_w1    + (size_t)l * FF * E;
        const float* b1   = f_b1    + (size_t)l * FF;
        const float* w2   = f_w2    + (size_t)l * E * FF;
        const float* b2   = f_b2    + (size_t)l * E;
        const float* g1   = ln1g + (size_t)l * E;
        const float* be1  = ln1b + (size_t)l * E;
        const float* g2   = ln2g + (size_t)l * E;
        const float* be2  = ln2b + (size_t)l * E;
        const float* g3   = ln3g + (size_t)l * E;
        const float* be3  = ln3b + (size_t)l * E;

        // --- self-attention ---
        launch_gemm(t, wqkv, bqkv, qkv, MQ, 3 * E, E, false);
        sa_attn_kernel<<<sa_grid, 128>>>(qkv, attn);
        launch_gemm(attn, wo, bo, proj, MQ, E, E, false);
        ln_kernel<<<MQ, E>>>(t, proj, g1, be1, t);

        // --- cross-attention ---
        launch_gemm(t, wq, bq, qb, MQ, E, E, false);
        launch_gemm(memory, wk, bk, kb, MK, E, E, false);
        launch_gemm(memory, wv, bv, vb, MK, E, E, false);
        ca_flash_kernel<<<ca_grid, 256>>>(qb, kb, vb, gmask, attn);
        launch_gemm(attn, wco, bco, proj, MQ, E, E, false);
        ln_kernel<<<MQ, E>>>(t, proj, g2, be2, t);

        // --- FFN ---
        launch_gemm(t, w1, b1, ffn, MQ, FF, E, true);
        launch_gemm(ffn, w2, b2, proj, MQ, E, FF, false);
        ln_kernel<<<MQ, E>>>(t, proj, g3, be3, t);
    }

    ln_kernel<<<MQ, E>>>(t, nullptr, lnfg, lnfb, (float*)d_out);
}

// round 6
// speedup vs baseline: 3.3879x; 1.1931x over previous
#include <cuda_runtime.h>
#include <cuda_bf16.h>
#include <math.h>
#include <stdint.h>

// Problem constants
#define B   8
#define NQ  300
#define NK  4096
#define E   256
#define H   8
#define D   32
#define FF  2048
#define LAYERS 6
#define ATTN_SCALE 0.17677669529663687f

#define TQ 16      // CA query tile
#define CK 128     // CA key chunk

#define MQ_ROWS (B * NQ)   // 2400
#define MK_ROWS (B * NK)   // 32768

// tcgen05 only exists in arch-specific ('a') compilation passes.
#if defined(__CUDA_ARCH_SPECIFIC__) || defined(__CUDA_ARCH_FEAT_SM103_ALL) || defined(__CUDA_ARCH_FEAT_SM100_ALL)
#define HAS_TC 1
#else
#define HAS_TC 0
#endif

// ---------------- fp32 scratch ----------------
__device__ float g_t[MQ_ROWS * E];
__device__ float g_qkv[MQ_ROWS * 3 * E];
__device__ float g_attn[MQ_ROWS * E];
__device__ float g_proj[MQ_ROWS * E];
__device__ float g_q[MQ_ROWS * E];
__device__ float g_k[MK_ROWS * E];
__device__ float g_v[MK_ROWS * E];
__device__ float g_ffn[MQ_ROWS * FF];

// ---------------- bf16 hi/lo scratch ----------------
#define OFF_WQKV 0
#define OFF_WO   1179648
#define OFF_WQ   1572864
#define OFF_WK   1966080
#define OFF_WV   2359296
#define OFF_WCO  2752512
#define OFF_W1   3145728
#define OFF_W2   6291456
#define W_TOTAL  9437184

__device__ __nv_bfloat16 g_whi[W_TOTAL];
__device__ __nv_bfloat16 g_wlo[W_TOTAL];
__device__ __nv_bfloat16 g_thi[MQ_ROWS * E],  g_tlo[MQ_ROWS * E];
__device__ __nv_bfloat16 g_ahi[MQ_ROWS * E],  g_alo[MQ_ROWS * E];
__device__ __nv_bfloat16 g_mhi[MK_ROWS * E],  g_mlo[MK_ROWS * E];
__device__ __nv_bfloat16 g_fhi[MQ_ROWS * FF], g_flo[MQ_ROWS * FF];

// ================= PTX helpers =================
__device__ __forceinline__ uint32_t smem_u32(const void* p) {
    uint32_t a;
    asm("{ .reg .u64 t; cvta.to.shared.u64 t, %1; cvt.u32.u64 %0, t; }" : "=r"(a) : "l"(p));
    return a;
}

#if HAS_TC
__device__ __forceinline__ uint32_t elect_one() {
    uint32_t pred;
    asm volatile("{.reg .pred p; elect.sync _|p, 0xFFFFFFFF; selp.b32 %0, 1, 0, p;}" : "=r"(pred));
    return pred;
}
#define TC_ALLOC(sm, n)  asm volatile("tcgen05.alloc.cta_group::1.sync.aligned.shared::cta.b32 [%0], %1;" :: "r"((uint32_t)(sm)), "r"((uint32_t)(n)) : "memory")
#define TC_DEALLOC(t, n) asm volatile("tcgen05.dealloc.cta_group::1.sync.aligned.b32 %0, %1;" :: "r"(t), "r"((uint32_t)(n)))
#define TC_RELINQ()      asm volatile("tcgen05.relinquish_alloc_permit.cta_group::1.sync.aligned;")
#define TC_COMMIT(mb)    asm volatile("tcgen05.commit.cta_group::1.mbarrier::arrive::one.shared::cluster.b64 [%0];" :: "r"((uint32_t)(mb)) : "memory")
#define TC_WAIT_LD()     asm volatile("tcgen05.wait::ld.sync.aligned;" ::: "memory")
#define TC_FENCE_AFTER() asm volatile("tcgen05.fence::after_thread_sync;" ::: "memory")
#define FENCE_ASYNC()    asm volatile("fence.proxy.async.shared::cta;" ::: "memory")
#define MBAR_INIT(mb, c) asm volatile("mbarrier.init.shared.b64 [%0], %1;" :: "r"((uint32_t)(mb)), "r"((uint32_t)(c)) : "memory")

#define MBAR_WAIT(mb, ph) do { \
    uint32_t _m = (uint32_t)(mb), _p = (uint32_t)(ph), _d; \
    asm volatile("{.reg .pred p; mbarrier.try_wait.parity.acquire.cta.shared::cta.b64 p, [%1], %2; selp.b32 %0, 1, 0, p;}" \
        : "=r"(_d) : "r"(_m), "r"(_p) : "memory"); \
    if (!_d) { \
        asm volatile("{.reg .pred P1; WL_%=: mbarrier.try_wait.parity.acquire.cta.shared::cta.b64 P1, [%0], %1, 0x989680;" \
            "@P1 bra.uni WD_%=; bra.uni WL_%=; WD_%=: }" :: "r"(_m), "r"(_p) : "memory"); \
    } \
} while (0)

#define TC_LD_X32(r, addr) \
    asm volatile("tcgen05.ld.sync.aligned.32x32b.x32.b32 " \
        "{%0,%1,%2,%3,%4,%5,%6,%7,%8,%9,%10,%11,%12,%13,%14,%15," \
        "%16,%17,%18,%19,%20,%21,%22,%23,%24,%25,%26,%27,%28,%29,%30,%31}, [%32];" \
        : "=r"((r)[0]),"=r"((r)[1]),"=r"((r)[2]),"=r"((r)[3]),"=r"((r)[4]),"=r"((r)[5]),"=r"((r)[6]),"=r"((r)[7]), \
          "=r"((r)[8]),"=r"((r)[9]),"=r"((r)[10]),"=r"((r)[11]),"=r"((r)[12]),"=r"((r)[13]),"=r"((r)[14]),"=r"((r)[15]), \
          "=r"((r)[16]),"=r"((r)[17]),"=r"((r)[18]),"=r"((r)[19]),"=r"((r)[20]),"=r"((r)[21]),"=r"((r)[22]),"=r"((r)[23]), \
          "=r"((r)[24]),"=r"((r)[25]),"=r"((r)[26]),"=r"((r)[27]),"=r"((r)[28]),"=r"((r)[29]),"=r"((r)[30]),"=r"((r)[31]) \
        : "r"(addr))

__device__ __forceinline__ void mma_f16_ss(uint32_t d, uint64_t a, uint64_t b,
                                           uint32_t idesc, bool acc) {
    uint32_t e = acc ? 1u : 0u;
    asm volatile(
        "{\n\t.reg .pred p;\n\tsetp.ne.u32 p, %4, 0;\n\t"
        "tcgen05.mma.cta_group::1.kind::f16 [%0], %1, %2, %3, {%5, %5, %5, %5}, p;\n\t}"
        :: "r"(d), "l"(a), "l"(b), "r"(idesc), "r"(e), "r"(0u) : "memory");
}
#endif // HAS_TC

#define SW128(x) ((x) ^ (((x) >> 3) & 0x70))
static constexpr uint64_t DESC_BASE_SW128 =
    (uint64_t(2) << 61) | (uint64_t(1) << 46) | (uint64_t(64) << 32) | (uint64_t(1) << 16);
#define MK_DESC(a) (DESC_BASE_SW128 | ((uint64_t)((a) >> 4) & 0x3FFF))

// idesc: F32 accum, bf16 A/B, M=128, N=128
#define TC_IDESC ((1u << 4) | (1u << 7) | (1u << 10) | (16u << 17) | (8u << 24))

// ================= tcgen05 split-bf16 GEMM =================
// offsets relative to 1024-aligned base
#define SM_MBAR   0
#define SM_TMEMP  16
#define SM_BIAS   512
#define SM_AHI    1024
#define SM_ALO    (1024 + 16384)
#define SM_BHI    (1024 + 32768)
#define SM_BLO    (1024 + 49152)
#define SM_TOTAL  (1024 + 65536 + 1024)   // +1KB alignment slack

template <int RELU>
__global__ void __launch_bounds__(128, 1) __cluster_dims__(1, 1, 1)
tc_gemm_kernel(const __nv_bfloat16* __restrict__ Ahi, const __nv_bfloat16* __restrict__ Alo,
               const __nv_bfloat16* __restrict__ Whi, const __nv_bfloat16* __restrict__ Wlo,
               const float* __restrict__ bias, float* __restrict__ C,
               int M, int N, int K) {
    extern __shared__ __align__(16) char smem_raw[];
    char* smem = (char*)((((uintptr_t)smem_raw) + 1023) & ~(uintptr_t)1023);
    const uint32_t sb = smem_u32(smem);
    const int tid = threadIdx.x;
    const int wid = tid >> 5, lane = tid & 31;
    const int n0 = blockIdx.x * 128;
    const int m0 = blockIdx.y * 128;
    (void)sb; (void)wid; (void)lane;

#if HAS_TC
    if (wid == 0) {
        TC_ALLOC(sb + SM_TMEMP, 128);
        TC_RELINQ();            // release alloc permit so peer CTAs on this SM can alloc
    }
    if (tid == 0) { MBAR_INIT(sb + SM_MBAR, 1); }
    if (tid < 128) ((float*)(smem + SM_BIAS))[tid] = bias[n0 + tid];
    __syncthreads();

    uint32_t tmem;
    asm volatile("ld.shared.b32 %0, [%1];" : "=r"(tmem) : "r"(sb + SM_TMEMP));

    const uint64_t dAhi = MK_DESC(sb + SM_AHI);
    const uint64_t dAlo = MK_DESC(sb + SM_ALO);
    const uint64_t dBhi = MK_DESC(sb + SM_BHI);
    const uint64_t dBlo = MK_DESC(sb + SM_BLO);

    const int nchunks = K >> 6;
    int phase = 0;

    for (int kc = 0; kc < nchunks; kc++) {
        const int kel = kc * 64;
#pragma unroll
        for (int it = 0; it < 32; it++) {
            int idx = it * 128 + tid;
            int tile = idx >> 10;
            int r = (idx >> 3) & 127;
            int c16 = idx & 7;
            uint4 val = make_uint4(0, 0, 0, 0);
            if (tile < 2) {
                int m = m0 + r;
                if (m < M) {
                    const __nv_bfloat16* src = (tile == 0) ? Ahi : Alo;
                    val = *(const uint4*)&src[(size_t)m * K + kel + c16 * 8];
                }
            } else {
                int n = n0 + r;
                const __nv_bfloat16* src = (tile == 2) ? Whi : Wlo;
                val = *(const uint4*)&src[(size_t)n * K + kel + c16 * 8];
            }
            uint32_t off = (tile == 0 ? SM_AHI : tile == 1 ? SM_ALO : tile == 2 ? SM_BHI : SM_BLO)
                         + SW128((uint32_t)(r * 128 + c16 * 16));
            *(uint4*)(smem + off) = val;
        }
        __syncthreads();

        if (wid == 0) {
            if (elect_one()) {
                FENCE_ASYNC();
                bool first = (kc == 0);
#pragma unroll
                for (int ks = 0; ks < 4; ks++)
                    mma_f16_ss(tmem, dAhi + ks * 2, dBhi + ks * 2, TC_IDESC, !(first && ks == 0));
#pragma unroll
                for (int ks = 0; ks < 4; ks++)
                    mma_f16_ss(tmem, dAhi + ks * 2, dBlo + ks * 2, TC_IDESC, true);
#pragma unroll
                for (int ks = 0; ks < 4; ks++)
                    mma_f16_ss(tmem, dAlo + ks * 2, dBhi + ks * 2, TC_IDESC, true);
                TC_COMMIT(sb + SM_MBAR);
            }
        }
        MBAR_WAIT(sb + SM_MBAR, phase);
        phase ^= 1;
        __syncthreads();
    }

    TC_FENCE_AFTER();

    const float* bsm = (const float*)(smem + SM_BIAS);
    const int m = m0 + wid * 32 + lane;
#pragma unroll
    for (int cc = 0; cc < 4; cc++) {
        uint32_t dr[32];
        TC_LD_X32(dr, tmem + cc * 32);
        TC_WAIT_LD();
        if (m < M) {
            float* crow = &C[(size_t)m * N + n0 + cc * 32];
#pragma unroll
            for (int c4 = 0; c4 < 8; c4++) {
                float4 o;
                o.x = __uint_as_float(dr[c4 * 4 + 0]) + bsm[cc * 32 + c4 * 4 + 0];
                o.y = __uint_as_float(dr[c4 * 4 + 1]) + bsm[cc * 32 + c4 * 4 + 1];
                o.z = __uint_as_float(dr[c4 * 4 + 2]) + bsm[cc * 32 + c4 * 4 + 2];
                o.w = __uint_as_float(dr[c4 * 4 + 3]) + bsm[cc * 32 + c4 * 4 + 3];
                if (RELU) {
                    o.x = fmaxf(o.x, 0.f); o.y = fmaxf(o.y, 0.f);
                    o.z = fmaxf(o.z, 0.f); o.w = fmaxf(o.w, 0.f);
                }
                *(float4*)&crow[c4 * 4] = o;
            }
        }
    }

    __syncthreads();
    if (wid == 0) { TC_DEALLOC(tmem, 128); }
#else
    // ---- generic-PTX fallback: correct fp32 path (slow; insurance only) ----
    const int m = m0 + tid;
    if (m < M) {
        for (int cg = 0; cg < 4; cg++) {
            float acc[32];
#pragma unroll
            for (int j = 0; j < 32; j++) acc[j] = bias[n0 + cg * 32 + j];
            for (int k = 0; k < K; k++) {
                float a = __bfloat162float(Ahi[(size_t)m * K + k]) +
                          __bfloat162float(Alo[(size_t)m * K + k]);
#pragma unroll
                for (int j = 0; j < 32; j++) {
                    int n = n0 + cg * 32 + j;
                    float w = __bfloat162float(Whi[(size_t)n * K + k]) +
                              __bfloat162float(Wlo[(size_t)n * K + k]);
                    acc[j] += a * w;
                }
            }
#pragma unroll
            for (int j = 0; j < 32; j++) {
                float v = acc[j];
                if (RELU) v = fmaxf(v, 0.f);
                C[(size_t)m * N + n0 + cg * 32 + j] = v;
            }
        }
    }
#endif
}

// ================= elementwise kernels =================
__global__ void copy_kernel(const float* __restrict__ s, float* __restrict__ d, int n) {
    int i = blockIdx.x * blockDim.x + threadIdx.x;
    if (i < n) d[i] = s[i];
}

__global__ void split_kernel(const float* __restrict__ x,
                             __nv_bfloat16* __restrict__ hi,
                             __nv_bfloat16* __restrict__ lo, int n) {
    int i = blockIdx.x * blockDim.x + threadIdx.x;
    if (i < n) {
        float v = x[i];
        __nv_bfloat16 h = __float2bfloat16_rn(v);
        hi[i] = h;
        lo[i] = __float2bfloat16_rn(v - __bfloat162float(h));
    }
}

// ================= self-attention =================
__global__ void sa_attn_kernel(const float* __restrict__ qkv, float* __restrict__ out) {
    const int q = blockIdx.x, h = blockIdx.y, b = blockIdx.z;
    const int tid = threadIdx.x;
    __shared__ float qs[D];
    __shared__ float sc[NQ];
    __shared__ float red[128];
    __shared__ float part[4][D];

    const float* qrow = qkv + (size_t)(b * NQ + q) * (3 * E) + h * D;
    if (tid < D) qs[tid] = qrow[tid];
    __syncthreads();

    for (int j = tid; j < NQ; j += 128) {
        const float* krow = qkv + (size_t)(b * NQ + j) * (3 * E) + E + h * D;
        float s = 0.f;
#pragma unroll
        for (int d = 0; d < D; d++) s += qs[d] * krow[d];
        sc[j] = s * ATTN_SCALE;
    }
    __syncthreads();

    float m = -INFINITY;
    for (int j = tid; j < NQ; j += 128) m = fmaxf(m, sc[j]);
    red[tid] = m;
    __syncthreads();
    for (int s = 64; s > 0; s >>= 1) {
        if (tid < s) red[tid] = fmaxf(red[tid], red[tid + s]);
        __syncthreads();
    }
    m = red[0];
    __syncthreads();

    float sum = 0.f;
    for (int j = tid; j < NQ; j += 128) {
        float e = __expf(sc[j] - m);
        sc[j] = e;
        sum += e;
    }
    red[tid] = sum;
    __syncthreads();
    for (int s = 64; s > 0; s >>= 1) {
        if (tid < s) red[tid] += red[tid + s];
        __syncthreads();
    }
    float inv = 1.f / red[0];
    __syncthreads();

    const int lane = tid & 31, grp = tid >> 5;
    float acc = 0.f;
    for (int j = grp; j < NQ; j += 4) {
        const float* vrow = qkv + (size_t)(b * NQ + j) * (3 * E) + 2 * E + h * D;
        acc += sc[j] * vrow[lane];
    }
    part[grp][lane] = acc;
    __syncthreads();
    if (tid < D) {
        float o = (part[0][tid] + part[1][tid] + part[2][tid] + part[3][tid]) * inv;
        out[(size_t)(b * NQ + q) * E + h * D + tid] = o;
    }
}

// ================= cross-attention flash =================
__global__ void __launch_bounds__(256)
ca_flash_kernel(const float* __restrict__ Q,
                const float* __restrict__ Kb,
                const float* __restrict__ Vb,
                const int* __restrict__ mask,
                float* __restrict__ out) {
    const int qt = blockIdx.x, h = blockIdx.y, b = blockIdx.z;
    const int tid = threadIdx.x;
    const int w = tid >> 5, lane = tid & 31;

    __shared__ __align__(16) float Ks[CK * 36];
    __shared__ __align__(16) float Vs[CK * 36];
    __shared__ __align__(16) float Qs[TQ * 36];
    __shared__ float Ps[8][CK];

    for (int i = tid; i < TQ * D; i += 256) {
        int ql = i >> 5, d = i & 31;
        int qg = qt * TQ + ql;
        if (qg >= NQ) qg = NQ - 1;
        Qs[ql * 36 + d] = Q[(size_t)(b * NQ + qg) * E + h * D + d];
    }
    __syncthreads();

    const int q0g = qt * TQ + w * 2;
    const int q1g = q0g + 1;
    const int q0c = (q0g < NQ) ? q0g : NQ - 1;
    const int q1c = (q1g < NQ) ? q1g : NQ - 1;
    const int* mrow[2] = { mask + (size_t)(b * NQ + q0c) * NK,
                           mask + (size_t)(b * NQ + q1c) * NK };

    float mv[2] = {-INFINITY, -INFINITY};
    float sv[2] = {0.f, 0.f};
    float av[2] = {0.f, 0.f};

    for (int k0 = 0; k0 < NK; k0 += CK) {
        for (int i = tid; i < CK * 8; i += 256) {
            int j = i >> 3, d4 = i & 7;
            size_t base = (size_t)(b * NK + k0 + j) * E + h * D + d4 * 4;
            *(float4*)&Ks[j * 36 + d4 * 4] = *(const float4*)&Kb[base];
            *(float4*)&Vs[j * 36 + d4 * 4] = *(const float4*)&Vb[base];
        }
        __syncthreads();

#pragma unroll
        for (int sub = 0; sub < 2; sub++) {
            const int ql = w * 2 + sub;
            float sc[4];
#pragma unroll
            for (int c = 0; c < 4; c++) {
                int key = c * 32 + lane;
                int mk = mrow[sub][k0 + key];
                float s;
                if (mk) {
                    s = 0.f;
#pragma unroll
                    for (int d4 = 0; d4 < 8; d4++) {
                        float4 kk = *(const float4*)&Ks[key * 36 + d4 * 4];
                        float4 qq = *(const float4*)&Qs[ql * 36 + d4 * 4];
                        s += kk.x * qq.x + kk.y * qq.y + kk.z * qq.z + kk.w * qq.w;
                    }
                    s *= ATTN_SCALE;
                } else {
                    s = -INFINITY;
                }
                sc[c] = s;
            }
            float cmax = fmaxf(fmaxf(sc[0], sc[1]), fmaxf(sc[2], sc[3]));
#pragma unroll
            for (int o = 16; o > 0; o >>= 1)
                cmax = fmaxf(cmax, __shfl_xor_sync(0xffffffff, cmax, o));

            float mOld = mv[sub];
            float mNew = fmaxf(mOld, cmax);
            float factor, psum = 0.f;
            if (mNew == -INFINITY) {
                factor = 1.f;
#pragma unroll
                for (int c = 0; c < 4; c++) Ps[w][c * 32 + lane] = 0.f;
            } else {
                factor = __expf(mOld - mNew);
#pragma unroll
                for (int c = 0; c < 4; c++) {
                    float p = (sc[c] == -INFINITY) ? 0.f : __expf(sc[c] - mNew);
                    psum += p;
                    Ps[w][c * 32 + lane] = p;
                }
            }
#pragma unroll
            for (int o = 16; o > 0; o >>= 1)
                psum += __shfl_xor_sync(0xffffffff, psum, o);
            __syncwarp();

            float a = av[sub] * factor;
#pragma unroll 4
            for (int j = 0; j < CK; j++)
                a += Ps[w][j] * Vs[j * 36 + lane];

            av[sub] = a;
            mv[sub] = mNew;
            sv[sub] = sv[sub] * factor + psum;
            __syncwarp();
        }
        __syncthreads();
    }

    if (q0g < NQ) {
        float inv = (sv[0] > 0.f) ? 1.f / sv[0] : 0.f;
        out[(size_t)(b * NQ + q0g) * E + h * D + lane] = av[0] * inv;
    }
    if (q1g < NQ) {
        float inv = (sv[1] > 0.f) ? 1.f / sv[1] : 0.f;
        out[(size_t)(b * NQ + q1g) * E + h * D + lane] = av[1] * inv;
    }
}

// ================= LayerNorm =================
__global__ void ln_kernel(const float* __restrict__ x,
                          const float* __restrict__ res,
                          const float* __restrict__ gamma,
                          const float* __restrict__ beta,
                          float* __restrict__ out) {
    const int row = blockIdx.x;
    const int tid = threadIdx.x;
    __shared__ float red[E];

    float v = x[(size_t)row * E + tid];
    if (res) v += res[(size_t)row * E + tid];

    red[tid] = v;
    __syncthreads();
    for (int s = 128; s > 0; s >>= 1) {
        if (tid < s) red[tid] += red[tid + s];
        __syncthreads();
    }
    float mean = red[0] * (1.f / E);
    __syncthreads();

    float d = v - mean;
    red[tid] = d * d;
    __syncthreads();
    for (int s = 128; s > 0; s >>= 1) {
        if (tid < s) red[tid] += red[tid + s];
        __syncthreads();
    }
    float var = red[0] * (1.f / E);
    float o = d * rsqrtf(var + 1e-5f) * gamma[tid] + beta[tid];
    out[(size_t)row * E + tid] = o;
}

// ================= host side =================
static inline void run_split(const float* x, __nv_bfloat16* hi, __nv_bfloat16* lo, int n) {
    split_kernel<<<(n + 255) / 256, 256>>>(x, hi, lo, n);
}

static inline void tc_gemm(const __nv_bfloat16* Ahi, const __nv_bfloat16* Alo,
                           const __nv_bfloat16* Whi, const __nv_bfloat16* Wlo,
                           const float* bias, float* C, int M, int N, int K, bool relu) {
    dim3 grid(N / 128, (M + 127) / 128);
    if (relu) tc_gemm_kernel<1><<<grid, 128, SM_TOTAL>>>(Ahi, Alo, Whi, Wlo, bias, C, M, N, K);
    else      tc_gemm_kernel<0><<<grid, 128, SM_TOTAL>>>(Ahi, Alo, Whi, Wlo, bias, C, M, N, K);
}

extern "C" void kernel_launch(void* const* d_in, const int* in_sizes, int n_in,
                              void* d_out, int out_size) {
    cudaFuncSetAttribute(tc_gemm_kernel<0>, cudaFuncAttributeMaxDynamicSharedMemorySize, SM_TOTAL);
    cudaFuncSetAttribute(tc_gemm_kernel<1>, cudaFuncAttributeMaxDynamicSharedMemorySize, SM_TOTAL);

    const float* tgt      = (const float*)d_in[0];
    const float* memory   = (const float*)d_in[1];
    const int*   gmask    = (const int*)d_in[2];
    const float* sa_wqkv  = (const float*)d_in[3];
    const float* sa_bqkv  = (const float*)d_in[4];
    const float* sa_wo    = (const float*)d_in[5];
    const float* sa_bo    = (const float*)d_in[6];
    const float* ca_wq    = (const float*)d_in[7];
    const float* ca_bq    = (const float*)d_in[8];
    const float* ca_wk    = (const float*)d_in[9];
    const float* ca_bk    = (const float*)d_in[10];
    const float* ca_wv    = (const float*)d_in[11];
    const float* ca_bv    = (const float*)d_in[12];
    const float* ca_wo    = (const float*)d_in[13];
    const float* ca_bo    = (const float*)d_in[14];
    const float* f_w1     = (const float*)d_in[15];
    const float* f_b1     = (const float*)d_in[16];
    const float* f_w2     = (const float*)d_in[17];
    const float* f_b2     = (const float*)d_in[18];
    const float* ln1g     = (const float*)d_in[19];
    const float* ln1b     = (const float*)d_in[20];
    const float* ln2g     = (const float*)d_in[21];
    const float* ln2b     = (const float*)d_in[22];
    const float* ln3g     = (const float*)d_in[23];
    const float* ln3b     = (const float*)d_in[24];
    const float* lnfg     = (const float*)d_in[25];
    const float* lnfb     = (const float*)d_in[26];

    float *t, *qkv, *attn, *proj, *qb, *kb, *vb, *ffn;
    cudaGetSymbolAddress((void**)&t,    g_t);
    cudaGetSymbolAddress((void**)&qkv,  g_qkv);
    cudaGetSymbolAddress((void**)&attn, g_attn);
    cudaGetSymbolAddress((void**)&proj, g_proj);
    cudaGetSymbolAddress((void**)&qb,   g_q);
    cudaGetSymbolAddress((void**)&kb,   g_k);
    cudaGetSymbolAddress((void**)&vb,   g_v);
    cudaGetSymbolAddress((void**)&ffn,  g_ffn);

    __nv_bfloat16 *whi, *wlo, *thi, *tlo, *ahi, *alo, *mhi, *mlo, *fhi, *flo;
    cudaGetSymbolAddress((void**)&whi, g_whi);
    cudaGetSymbolAddress((void**)&wlo, g_wlo);
    cudaGetSymbolAddress((void**)&thi, g_thi);
    cudaGetSymbolAddress((void**)&tlo, g_tlo);
    cudaGetSymbolAddress((void**)&ahi, g_ahi);
    cudaGetSymbolAddress((void**)&alo, g_alo);
    cudaGetSymbolAddress((void**)&mhi, g_mhi);
    cudaGetSymbolAddress((void**)&mlo, g_mlo);
    cudaGetSymbolAddress((void**)&fhi, g_fhi);
    cudaGetSymbolAddress((void**)&flo, g_flo);

    // ---- weight + memory splits ----
    run_split(sa_wqkv, whi + OFF_WQKV, wlo + OFF_WQKV, LAYERS * 3 * E * E);
    run_split(sa_wo,   whi + OFF_WO,   wlo + OFF_WO,   LAYERS * E * E);
    run_split(ca_wq,   whi + OFF_WQ,   wlo + OFF_WQ,   LAYERS * E * E);
    run_split(ca_wk,   whi + OFF_WK,   wlo + OFF_WK,   LAYERS * E * E);
    run_split(ca_wv,   whi + OFF_WV,   wlo + OFF_WV,   LAYERS * E * E);
    run_split(ca_wo,   whi + OFF_WCO,  wlo + OFF_WCO,  LAYERS * E * E);
    run_split(f_w1,    whi + OFF_W1,   wlo + OFF_W1,   LAYERS * FF * E);
    run_split(f_w2,    whi + OFF_W2,   wlo + OFF_W2,   LAYERS * E * FF);
    run_split(memory,  mhi, mlo, MK_ROWS * E);

    copy_kernel<<<(MQ_ROWS * E + 255) / 256, 256>>>(tgt, t, MQ_ROWS * E);
    run_split(t, thi, tlo, MQ_ROWS * E);

    dim3 sa_grid(NQ, H, B);
    dim3 ca_grid((NQ + TQ - 1) / TQ, H, B);

    for (int l = 0; l < LAYERS; l++) {
        const size_t wEE = (size_t)l * E * E;
        const __nv_bfloat16* wqkv_h = whi + OFF_WQKV + (size_t)l * 3 * E * E;
        const __nv_bfloat16* wqkv_l = wlo + OFF_WQKV + (size_t)l * 3 * E * E;
        const float* bqkv = sa_bqkv + (size_t)l * 3 * E;
        const float* bo   = sa_bo + (size_t)l * E;
        const float* bq   = ca_bq + (size_t)l * E;
        const float* bk   = ca_bk + (size_t)l * E;
        const float* bv   = ca_bv + (size_t)l * E;
        const float* bco  = ca_bo + (size_t)l * E;
        const float* b1   = f_b1 + (size_t)l * FF;
        const float* b2   = f_b2 + (size_t)l * E;
        const float* g1   = ln1g + (size_t)l * E;
        const float* be1  = ln1b + (size_t)l * E;
        const float* g2   = ln2g + (size_t)l * E;
        const float* be2  = ln2b + (size_t)l * E;
        const float* g3   = ln3g + (size_t)l * E;
        const float* be3  = ln3b + (size_t)l * E;

        // --- self-attention ---
        tc_gemm(thi, tlo, wqkv_h, wqkv_l, bqkv, qkv, MQ_ROWS, 3 * E, E, false);
        sa_attn_kernel<<<sa_grid, 128>>>(qkv, attn);
        run_split(attn, ahi, alo, MQ_ROWS * E);
        tc_gemm(ahi, alo, whi + OFF_WO + wEE, wlo + OFF_WO + wEE, bo, proj, MQ_ROWS, E, E, false);
        ln_kernel<<<MQ_ROWS, E>>>(t, proj, g1, be1, t);
        run_split(t, thi, tlo, MQ_ROWS * E);

        // --- cross-attention ---
        tc_gemm(thi, tlo, whi + OFF_WQ + wEE, wlo + OFF_WQ + wEE, bq, qb, MQ_ROWS, E, E, false);
        tc_gemm(mhi, mlo, whi + OFF_WK + wEE, wlo + OFF_WK + wEE, bk, kb, MK_ROWS, E, E, false);
        tc_gemm(mhi, mlo, whi + OFF_WV + wEE, wlo + OFF_WV + wEE, bv, vb, MK_ROWS, E, E, false);
        ca_flash_kernel<<<ca_grid, 256>>>(qb, kb, vb, gmask, attn);
        run_split(attn, ahi, alo, MQ_ROWS * E);
        tc_gemm(ahi, alo, whi + OFF_WCO + wEE, wlo + OFF_WCO + wEE, bco, proj, MQ_ROWS, E, E, false);
        ln_kernel<<<MQ_ROWS, E>>>(t, proj, g2, be2, t);
        run_split(t, thi, tlo, MQ_ROWS * E);

        // --- FFN ---
        tc_gemm(thi, tlo, whi + OFF_W1 + (size_t)l * FF * E, wlo + OFF_W1 + (size_t)l * FF * E,
                b1, ffn, MQ_ROWS, FF, E, true);
        run_split(ffn, fhi, flo, MQ_ROWS * FF);
        tc_gemm(fhi, flo, whi + OFF_W2 + (size_t)l * E * FF, wlo + OFF_W2 + (size_t)l * E * FF,
                b2, proj, MQ_ROWS, E, FF, false);
        ln_kernel<<<MQ_ROWS, E>>>(t, proj, g3, be3, t);
        run_split(t, thi, tlo, MQ_ROWS * E);
    }

    ln_kernel<<<MQ_ROWS, E>>>(t, nullptr, lnfg, lnfb, (float*)d_out);
}